// round 13
// baseline (speedup 1.0000x reference)
#include <cuda_runtime.h>
#include <cstdint>
#include <math.h>

// ---------------------------------------------------------------------------
// Problem dims
// ---------------------------------------------------------------------------
#define T_STEPS 8192
#define IN_DIM  109
#define H_DIM   1024
#define G_DIM   4096   // 4*H
#define NBLK    128    // persistent blocks (<=148 SMs, 1 CTA/SM -> co-resident)

// ---------------------------------------------------------------------------
// Scratch (static device allocations; no cudaMalloc allowed)
// ---------------------------------------------------------------------------
__device__ float g_xproj[(size_t)T_STEPS * G_DIM];   // reused for both layers
__device__ float g_h0[(size_t)T_STEPS * H_DIM];
__device__ float g_h1[(size_t)T_STEPS * H_DIM];
__device__ float g_hbuf[2][2 * H_DIM];               // [layer][parity*1024 + j]
// Per-group cumulative counters: [layer*2 + group] at stride 32 (own lines).
// Group g = blocks [64g, 64g+64). Counter == 64*t <=> group done step t-1.
__device__ unsigned g_grp[4 * 32];

// ---------------------------------------------------------------------------
// Memory-order helpers
// ---------------------------------------------------------------------------
__device__ __forceinline__ unsigned ld_acq_u(const unsigned* p) {
    unsigned v;
    asm volatile("ld.acquire.gpu.b32 %0, [%1];" : "=r"(v) : "l"(p) : "memory");
    return v;
}
__device__ __forceinline__ void red_add_release(unsigned* p, unsigned v) {
    asm volatile("red.release.gpu.global.add.u32 [%0], %1;" :: "l"(p), "r"(v) : "memory");
}
__device__ __forceinline__ int ld_acq_cta(const int* p) {
    int v;
    asm volatile("ld.acquire.cta.b32 %0, [%1];" : "=r"(v) : "l"(p) : "memory");
    return v;
}
__device__ __forceinline__ void st_rel_cta(int* p, int v) {
    asm volatile("st.release.cta.b32 [%0], %1;" :: "l"(p), "r"(v) : "memory");
}
__device__ __forceinline__ float4 ld_cv4(const float4* p) {
    float4 v;
    asm volatile("ld.global.cv.v4.f32 {%0,%1,%2,%3}, [%4];"
                 : "=f"(v.x), "=f"(v.y), "=f"(v.z), "=f"(v.w) : "l"(p) : "memory");
    return v;
}
__device__ __forceinline__ void st_cg(float* p, float v) {
    asm volatile("st.global.cg.f32 [%0], %1;" :: "l"(p), "f"(v) : "memory");
}

// ---- packed f32x2 (sm_100+) -----------------------------------------------
__device__ __forceinline__ unsigned long long pack2(float lo, float hi) {
    unsigned long long r;
    asm("mov.b64 %0, {%1, %2};" : "=l"(r) : "f"(lo), "f"(hi));
    return r;
}
__device__ __forceinline__ unsigned long long ffma2(
    unsigned long long a, unsigned long long b, unsigned long long c) {
    unsigned long long d;
    asm("fma.rn.f32x2 %0, %1, %2, %3;" : "=l"(d) : "l"(a), "l"(b), "l"(c));
    return d;
}
__device__ __forceinline__ void unpack2(unsigned long long v, float& lo, float& hi) {
    asm("mov.b64 {%0, %1}, %2;" : "=f"(lo), "=f"(hi) : "l"(v));
}

// ---- fast-accurate activations (abs err ~1e-6; R12-proven) ----------------
__device__ __forceinline__ float sig_fast(float x) {
    return __fdividef(1.0f, 1.0f + __expf(-x));
}

// ---------------------------------------------------------------------------
// Init: zero group counters (every launch; graph replays reuse statics)
// ---------------------------------------------------------------------------
__global__ void init_kernel() {
    int i = blockIdx.x * blockDim.x + threadIdx.x;
    if (i < 4 * 32) g_grp[i] = 0u;
}

// ---------------------------------------------------------------------------
// GEMM tile body: C[m0..+128][n0..+128] = A@B^T + bias1 + bias2 (R1-proven)
// ---------------------------------------------------------------------------
__device__ void gemm_tile_body(
    const float* A, const float* B,
    const float* bias1, const float* bias2,
    float* C, int N, int K, int m0, int n0)
{
    __shared__ float As[8][132];
    __shared__ float Bs[8][132];

    const int tid = threadIdx.x;
    const int lr  = tid >> 1;
    const int lk4 = (tid & 1) * 4;
    const int ty  = tid >> 4;
    const int tx  = tid & 15;

    float acc[8][8];
#pragma unroll
    for (int i = 0; i < 8; i++)
#pragma unroll
        for (int j = 0; j < 8; j++) acc[i][j] = 0.0f;

    for (int k0 = 0; k0 < K; k0 += 8) {
#pragma unroll
        for (int e = 0; e < 4; e++) {
            int k = k0 + lk4 + e;
            float av = 0.0f, bv = 0.0f;
            if (k < K) {
                av = A[(size_t)(m0 + lr) * K + k];
                bv = B[(size_t)(n0 + lr) * K + k];
            }
            As[lk4 + e][lr] = av;
            Bs[lk4 + e][lr] = bv;
        }
        __syncthreads();
#pragma unroll
        for (int kk = 0; kk < 8; kk++) {
            float a[8], b[8];
            float4 a0 = *(const float4*)&As[kk][ty * 8];
            float4 a1 = *(const float4*)&As[kk][ty * 8 + 4];
            float4 b0 = *(const float4*)&Bs[kk][tx * 8];
            float4 b1 = *(const float4*)&Bs[kk][tx * 8 + 4];
            a[0]=a0.x; a[1]=a0.y; a[2]=a0.z; a[3]=a0.w;
            a[4]=a1.x; a[5]=a1.y; a[6]=a1.z; a[7]=a1.w;
            b[0]=b0.x; b[1]=b0.y; b[2]=b0.z; b[3]=b0.w;
            b[4]=b1.x; b[5]=b1.y; b[6]=b1.z; b[7]=b1.w;
#pragma unroll
            for (int i = 0; i < 8; i++)
#pragma unroll
                for (int j = 0; j < 8; j++)
                    acc[i][j] = fmaf(a[i], b[j], acc[i][j]);
        }
        __syncthreads();
    }

#pragma unroll
    for (int i = 0; i < 8; i++) {
        size_t row = (size_t)(m0 + ty * 8 + i) * N;
#pragma unroll
        for (int j = 0; j < 8; j++) {
            int n = n0 + tx * 8 + j;
            C[row + n] = acc[i][j] + bias1[n] + bias2[n];
        }
    }
}

// Standalone GEMM (x_proj0, K=109)
__global__ __launch_bounds__(256) void gemm_nt_bias(
    const float* __restrict__ A, const float* __restrict__ B,
    const float* __restrict__ bias1, const float* __restrict__ bias2,
    float* __restrict__ C, int N, int K)
{
    gemm_tile_body(A, B, bias1, bias2, C, N, K, blockIdx.y * 128, blockIdx.x * 128);
}

// ---------------------------------------------------------------------------
// LSTM recurrence body. NEW this round (group-split exchange):
//  * thread (rg,cg) covers CONTIGUOUS cols [cg*16, cg*16+16); warp's h source
//    is a single block-group (half = warp&1; cols [512*half, 512*half+512)).
//  * producers RED per-group counters; lane0 of warps 0/1 polls its own group
//    and releases a smem flag; warps spin the flag (no L2 traffic) then load
//    h DIRECTLY into registers (no smem staging, no pre-matvec barriers).
//  * early group's fetch+FFMA2 overlaps late group's arrival; the single
//    __syncthreads before the tail joins both groups -> same global WAR
//    invariant as R9/R10 (write slot t&1 only after all blocks did step t-1).
// ---------------------------------------------------------------------------
__device__ void lstm_body(
    const float* __restrict__ Whh,   // [4096][1024]
    const float* xp,                 // [8192][4096] (may alias GEMM output)
    float* h_all,                    // [8192][1024]
    float* hbuf,                     // [2*1024]
    unsigned* grp)                   // 2 counters at stride 32
{
    const int b    = blockIdx.x;
    const int tid  = threadIdx.x;
    const int rg   = tid >> 6;       // gate 0..3 (i,f,g,o)
    const int cg   = tid & 63;       // 0..63 -> cols [cg*16, cg*16+16)
    const int lane = tid & 31;
    const int warp = tid >> 5;
    const int half = warp & 1;       // consumer group (== cg>>5, warp-uniform)

    __shared__ float red[4][2][8];
    __shared__ float actbuf[32];
    __shared__ int   gprog[2];

    // Weights packed as row-pairs over contiguous cols:
    // w2[p][c] = (row rg*1024+b*8+2p, row +1) at col cg*16 + c.
    unsigned long long w2[4][16];
#pragma unroll
    for (int p = 0; p < 4; p++) {
        const float* wr0 = Whh + (size_t)(rg * 1024 + b * 8 + 2 * p) * 1024 + cg * 16;
        const float* wr1 = wr0 + 1024;
#pragma unroll
        for (int e4 = 0; e4 < 4; e4++) {
            float4 a = *(const float4*)(wr0 + e4 * 4);
            float4 c = *(const float4*)(wr1 + e4 * 4);
            w2[p][e4 * 4 + 0] = pack2(a.x, c.x);
            w2[p][e4 * 4 + 1] = pack2(a.y, c.y);
            w2[p][e4 * 4 + 2] = pack2(a.z, c.z);
            w2[p][e4 * 4 + 3] = pack2(a.w, c.w);
        }
    }

    if (tid < 2) gprog[tid] = 0;
    float c_state = 0.0f;            // meaningful for tid < 8
    __syncthreads();

    for (int t = 0; t < T_STEPS; ++t) {
        // x_proj prefetch: warp 0, lane (4*jj+g) -> gate g of element jj.
        float xv = 0.0f;
        if (tid < 32)
            xv = __ldcs(xp + (size_t)t * G_DIM + (tid & 3) * H_DIM + b * 8 + (tid >> 2));

        // Group wait + direct register fetch (per-warp; groups independent).
        float4 hq[4];
        if (t > 0) {
            if (warp < 2 && lane == 0) {
                const unsigned* gp = grp + warp * 32;
                const unsigned tgt = 64u * (unsigned)t;
                while (ld_acq_u(gp) < tgt) { }
                st_rel_cta(&gprog[warp], t);
            }
            while (ld_acq_cta(&gprog[half]) < t) { }
            const float4* src = (const float4*)(hbuf + ((t + 1) & 1) * H_DIM + cg * 16);
            hq[0] = ld_cv4(src);
            hq[1] = ld_cv4(src + 1);
            hq[2] = ld_cv4(src + 2);
            hq[3] = ld_cv4(src + 3);
        } else {
#pragma unroll
            for (int e4 = 0; e4 < 4; e4++) hq[e4] = make_float4(0.f, 0.f, 0.f, 0.f);
        }

        // Mat-vec: 4 row-pairs x 16 contiguous cols via FFMA2.
        unsigned long long acc2[4];
#pragma unroll
        for (int p = 0; p < 4; p++) acc2[p] = 0ull;
#pragma unroll
        for (int e4 = 0; e4 < 4; e4++) {
            unsigned long long hx = pack2(hq[e4].x, hq[e4].x);
            unsigned long long hy = pack2(hq[e4].y, hq[e4].y);
            unsigned long long hz = pack2(hq[e4].z, hq[e4].z);
            unsigned long long hw = pack2(hq[e4].w, hq[e4].w);
#pragma unroll
            for (int p = 0; p < 4; p++) {
                acc2[p] = ffma2(w2[p][e4 * 4 + 0], hx, acc2[p]);
                acc2[p] = ffma2(w2[p][e4 * 4 + 1], hy, acc2[p]);
                acc2[p] = ffma2(w2[p][e4 * 4 + 2], hz, acc2[p]);
                acc2[p] = ffma2(w2[p][e4 * 4 + 3], hw, acc2[p]);
            }
        }
        float acc[8];
#pragma unroll
        for (int p = 0; p < 4; p++) unpack2(acc2[p], acc[2 * p], acc[2 * p + 1]);

        // Butterfly: warp sums its 512-col half for all 8 rows of gate rg.
#pragma unroll
        for (int i = 0; i < 8; i++) {
#pragma unroll
            for (int off = 16; off > 0; off >>= 1)
                acc[i] += __shfl_xor_sync(0xFFFFFFFFu, acc[i], off);
        }
        if (lane == 0) {
#pragma unroll
            for (int i = 0; i < 8; i++) red[rg][half][i] = acc[i];
        }
        __syncthreads();   // joins BOTH group waits -> global WAR invariant

        // Tail (R12-proven): warp 0 computes 32 activations in parallel;
        // threads 0..7 combine; publish hbuf; RED own group; h_all store.
        if (tid < 32) {
            const int jj = tid >> 2;
            const int g  = tid & 3;
            float pre = red[g][0][jj] + red[g][1][jj] + xv;
            float arg = (g == 2) ? (pre + pre) : pre;
            float s   = sig_fast(arg);
            actbuf[tid] = (g == 2) ? fmaf(2.0f, s, -1.0f) : s;
            __syncwarp(0xFFFFFFFFu);

            if (tid < 8) {
                float ig = actbuf[tid * 4 + 0];
                float fg = actbuf[tid * 4 + 1];
                float gg = actbuf[tid * 4 + 2];
                float og = actbuf[tid * 4 + 3];
                c_state = fg * c_state + ig * gg;
                float s2 = sig_fast(c_state + c_state);     // tanh(c)=2*sig(2c)-1
                float h  = og * fmaf(2.0f, s2, -1.0f);
                hbuf[(t & 1) * H_DIM + b * 8 + tid] = h;
                __syncwarp(0x000000FFu);
                if (tid == 0) {
                    red_add_release(grp + (b >> 6) * 32, 1u);
                }
                __syncwarp(0x000000FFu);
                st_cg(h_all + (size_t)t * H_DIM + b * 8 + tid, h);
            }
        }
    }

    // Final bump: publishes last h_all rows; gate max = 64*(T_STEPS+1)/group.
    __syncthreads();
    if (tid == 0) {
        red_add_release(grp + (b >> 6) * 32, 1u);
    }
}

// ---------------------------------------------------------------------------
// Fused kernel A: blocks 0..127 = layer-0 recurrence. Blocks 128.. = gated
// GEMM1 tiles. Gate BOTH groups >= 64*(m0+129): h0 rows <= m0+127 visible,
// xproj0 rows <= m0+128 consumed (WAR-safe). 1 poller/tile + backoff.
// ---------------------------------------------------------------------------
__global__ __launch_bounds__(256, 1) void fused_l0_gemm1(
    const float* __restrict__ Whh0,
    float* xproj,
    float* __restrict__ h0,
    float* hbuf, unsigned* grp,
    const float* __restrict__ Wih1,
    const float* __restrict__ b_ih1, const float* __restrict__ b_hh1)
{
    if (blockIdx.x < NBLK) {
        lstm_body(Whh0, xproj, h0, hbuf, grp);
    } else {
        const int tile = blockIdx.x - NBLK;       // 0..2047
        const int n0 = (tile & 31) * 128;
        const int m0 = (tile >> 5) * 128;
        const unsigned tgt = 64u * (unsigned)(m0 + 129);
        if (threadIdx.x == 0) {
            while (ld_acq_u(grp) < tgt || ld_acq_u(grp + 32) < tgt)
                __nanosleep(1024);
        }
        __syncthreads();
        gemm_tile_body(h0, Wih1, b_ih1, b_hh1, xproj, G_DIM, H_DIM, m0, n0);
    }
}

// ---------------------------------------------------------------------------
// FC (109 outputs) + log_softmax body. 8 timesteps per block.
// ---------------------------------------------------------------------------
__device__ void fc_body(
    const float* __restrict__ H, const float* __restrict__ Wf,
    const float* __restrict__ bf, float* __restrict__ out, int t0)
{
    __shared__ float ws[IN_DIM][68];
    __shared__ float hsm[8][68];
    __shared__ float lg[8][112];

    const int tid = threadIdx.x;
    const int tt  = tid & 7;
    const int n4  = tid >> 3;

    float acc[4] = {0.f, 0.f, 0.f, 0.f};

    for (int kc = 0; kc < H_DIM; kc += 64) {
        for (int idx = tid; idx < IN_DIM * 16; idx += 256) {
            int n = idx >> 4, k4 = idx & 15;
            *(float4*)&ws[n][k4 * 4] = *(const float4*)&Wf[(size_t)n * H_DIM + kc + k4 * 4];
        }
        for (int idx = tid; idx < 8 * 16; idx += 256) {
            int r = idx >> 4, k4 = idx & 15;
            *(float4*)&hsm[r][k4 * 4] = *(const float4*)&H[(size_t)(t0 + r) * H_DIM + kc + k4 * 4];
        }
        __syncthreads();
#pragma unroll
        for (int k4 = 0; k4 < 16; k4++) {
            float4 hv = *(const float4*)&hsm[tt][k4 * 4];
#pragma unroll
            for (int i = 0; i < 4; i++) {
                int n = n4 + i * 32;
                if (n < IN_DIM) {
                    float4 wv = *(const float4*)&ws[n][k4 * 4];
                    acc[i] += hv.x * wv.x + hv.y * wv.y + hv.z * wv.z + hv.w * wv.w;
                }
            }
        }
        __syncthreads();
    }

#pragma unroll
    for (int i = 0; i < 4; i++) {
        int n = n4 + i * 32;
        if (n < IN_DIM) lg[tt][n] = acc[i] + bf[n];
    }
    __syncthreads();

    const int wp = tid >> 5, lane = tid & 31;
    {
        int t = wp;
        float v0 = (lane       < IN_DIM) ? lg[t][lane]       : -INFINITY;
        float v1 = (lane + 32  < IN_DIM) ? lg[t][lane + 32]  : -INFINITY;
        float v2 = (lane + 64  < IN_DIM) ? lg[t][lane + 64]  : -INFINITY;
        float v3 = (lane + 96  < IN_DIM) ? lg[t][lane + 96]  : -INFINITY;
        float mx = fmaxf(fmaxf(v0, v1), fmaxf(v2, v3));
#pragma unroll
        for (int o = 16; o > 0; o >>= 1) mx = fmaxf(mx, __shfl_xor_sync(0xFFFFFFFFu, mx, o));
        float se = expf(v0 - mx) + expf(v1 - mx) + expf(v2 - mx) + expf(v3 - mx);
#pragma unroll
        for (int o = 16; o > 0; o >>= 1) se += __shfl_xor_sync(0xFFFFFFFFu, se, o);
        float ls = mx + logf(se);
        size_t row = (size_t)(t0 + t) * IN_DIM;
        if (lane      < IN_DIM) out[row + lane]      = v0 - ls;
        if (lane + 32 < IN_DIM) out[row + lane + 32] = v1 - ls;
        if (lane + 64 < IN_DIM) out[row + lane + 64] = v2 - ls;
        if (lane + 96 < IN_DIM) out[row + lane + 96] = v3 - ls;
    }
}

// ---------------------------------------------------------------------------
// Fused kernel B: blocks 0..127 = layer-1 recurrence. Blocks 128..1151 =
// gated FC tiles (both groups >= 64*(t0+9) -> h1 rows <= t0+7 visible).
// ---------------------------------------------------------------------------
__global__ __launch_bounds__(256, 1) void fused_l1_fc(
    const float* __restrict__ Whh1,
    const float* __restrict__ xproj,
    float* __restrict__ h1,
    float* hbuf, unsigned* grp,
    const float* __restrict__ fc_w, const float* __restrict__ fc_b,
    float* __restrict__ out)
{
    if (blockIdx.x < NBLK) {
        lstm_body(Whh1, xproj, h1, hbuf, grp);
    } else {
        const int t0 = (blockIdx.x - NBLK) * 8;
        const unsigned tgt = 64u * (unsigned)(t0 + 9);
        if (threadIdx.x == 0) {
            while (ld_acq_u(grp) < tgt || ld_acq_u(grp + 32) < tgt)
                __nanosleep(1024);
        }
        __syncthreads();
        fc_body(h1, fc_w, fc_b, out, t0);
    }
}

// ---------------------------------------------------------------------------
// Launch
// ---------------------------------------------------------------------------
extern "C" void kernel_launch(void* const* d_in, const int* in_sizes, int n_in,
                              void* d_out, int out_size)
{
    const float* input  = (const float*)d_in[0];   // [8192,109]
    const float* W_ih0  = (const float*)d_in[1];   // [4096,109]
    const float* W_hh0  = (const float*)d_in[2];   // [4096,1024]
    const float* b_ih0  = (const float*)d_in[3];
    const float* b_hh0  = (const float*)d_in[4];
    const float* W_ih1  = (const float*)d_in[5];   // [4096,1024]
    const float* W_hh1  = (const float*)d_in[6];   // [4096,1024]
    const float* b_ih1  = (const float*)d_in[7];
    const float* b_hh1  = (const float*)d_in[8];
    const float* fc_w   = (const float*)d_in[9];   // [109,1024]
    const float* fc_b   = (const float*)d_in[10];
    float* out = (float*)d_out;

    static float* p_xproj = nullptr;
    static float* p_h0 = nullptr;
    static float* p_h1 = nullptr;
    static float* p_hbuf = nullptr;
    static unsigned* p_grp = nullptr;
    if (!p_xproj) {
        cudaGetSymbolAddress((void**)&p_xproj, g_xproj);
        cudaGetSymbolAddress((void**)&p_h0,    g_h0);
        cudaGetSymbolAddress((void**)&p_h1,    g_h1);
        cudaGetSymbolAddress((void**)&p_hbuf,  g_hbuf);
        cudaGetSymbolAddress((void**)&p_grp,   g_grp);
    }

    // 1) reset group counters
    init_kernel<<<1, 256>>>();

    // 2) x_proj0 = input @ W_ih0^T + b_ih0 + b_hh0  (K=109)
    {
        dim3 grid(G_DIM / 128, T_STEPS / 128);
        gemm_nt_bias<<<grid, 256>>>(input, W_ih0, b_ih0, b_hh0,
                                    p_xproj, G_DIM, IN_DIM);
    }

    // 3) layer-0 recurrence + gated GEMM1 (xproj1) overlapped
    fused_l0_gemm1<<<NBLK + 2048, 256>>>(W_hh0, p_xproj, p_h0,
                                         p_hbuf + 0, p_grp + 0,
                                         W_ih1, b_ih1, b_hh1);

    // 4) layer-1 recurrence + gated FC/log_softmax overlapped
    fused_l1_fc<<<NBLK + T_STEPS / 8, 256>>>(W_hh1, p_xproj, p_h1,
                                             p_hbuf + 2 * H_DIM, p_grp + 64,
                                             fc_w, fc_b, out);
}